// round 4
// baseline (speedup 1.0000x reference)
#include <cuda_runtime.h>

#define N_NODES 50000
#define N_EDGES 800000
#define NF      128
#define HID     256
#define HEADS   8
#define CH      32
#define NG      128
#define OUT_DIM 10
#define SLOPE   0.2f

// ---------------- scratch (device globals; no allocation) ----------------
__device__ float g_h [(size_t)N_NODES * HID];
__device__ float g_fa[(size_t)N_NODES * HID];
__device__ float g_fb[(size_t)N_NODES * HID];
__device__ float g_als[N_NODES * HEADS];
__device__ float g_ald[N_NODES * HEADS];
__device__ int   g_cnt[N_NODES];
__device__ int   g_rowptr[N_NODES + 1];
__device__ int   g_col[N_EDGES];
__device__ int   g_blk[128];
__device__ int   g_is64_edge;
__device__ int   g_is64_batch;

__device__ __forceinline__ float* buf_sel(int s) {
    return (s == 0) ? g_h : (s == 1) ? g_fa : g_fb;
}

// dtype-agnostic index load: w = buffer viewed as 32-bit words
__device__ __forceinline__ int ld_idx(const int* __restrict__ w, int i, int is64) {
    return is64 ? w[2 * i] : w[i];   // little-endian low word
}

// ---------------- dtype detection (int64 vs int32 index tensors) ----------------
__global__ void detect_dtype(const int* __restrict__ ei_w, const int* __restrict__ b_w) {
    // edge_index: probe first 512 odd words. int64 -> high words all 0.
    // int32 -> random node ids in [0,50000), essentially never all zero.
    int acc = 0;
    for (int i = 0; i < 512; i++) acc |= ei_w[2 * i + 1];
    g_is64_edge = (acc == 0) ? 1 : 0;
    // batch: probe odd words near the END (sorted, tail values ~127 != 0).
    // Word indices < N_NODES are in-bounds for both dtypes.
    int accb = 0;
    for (int i = N_NODES - 512; i < N_NODES; i += 2) accb |= b_w[i | 1];
    g_is64_batch = (accb == 0) ? 1 : 0;
}

// ---------------- small utility kernels ----------------
__global__ void zero_cnt() {
    int i = blockIdx.x * blockDim.x + threadIdx.x;
    if (i < N_NODES) g_cnt[i] = 0;
}

__global__ void hist_kernel(const int* __restrict__ ei_w) {
    int e = blockIdx.x * blockDim.x + threadIdx.x;
    int is64 = g_is64_edge;
    if (e < N_EDGES) {
        int d = ld_idx(ei_w, N_EDGES + e, is64);
        atomicAdd(&g_cnt[d], 1);
    }
}

// block-level exclusive scan (1024 elems / block), writes block totals
__global__ void scan_block() {
    __shared__ int s[1024];
    int tid = threadIdx.x;
    int i = blockIdx.x * 1024 + tid;
    int v = (i < N_NODES) ? g_cnt[i] : 0;
    s[tid] = v;
    __syncthreads();
    for (int off = 1; off < 1024; off <<= 1) {
        int a = (tid >= off) ? s[tid - off] : 0;
        __syncthreads();
        s[tid] += a;
        __syncthreads();
    }
    if (i < N_NODES) g_rowptr[i] = s[tid] - v;   // exclusive within block
    if (tid == 1023) g_blk[blockIdx.x] = s[1023]; // block total
}

__global__ void scan_top(int n) {
    __shared__ int s[64];
    int tid = threadIdx.x;
    int v = (tid < n) ? g_blk[tid] : 0;
    s[tid] = v;
    __syncthreads();
    for (int off = 1; off < 64; off <<= 1) {
        int a = (tid >= off) ? s[tid - off] : 0;
        __syncthreads();
        s[tid] += a;
        __syncthreads();
    }
    if (tid < n) g_blk[tid] = s[tid] - v; // exclusive
}

__global__ void scan_add() {
    int i = blockIdx.x * 1024 + threadIdx.x;
    if (i < N_NODES) g_rowptr[i] += g_blk[i >> 10];
    if (i == 0) g_rowptr[N_NODES] = N_EDGES;
}

__global__ void scatter_kernel(const int* __restrict__ ei_w) {
    int e = blockIdx.x * blockDim.x + threadIdx.x;
    int is64 = g_is64_edge;
    if (e < N_EDGES) {
        int d = ld_idx(ei_w, N_EDGES + e, is64);
        int s = ld_idx(ei_w, e, is64);
        int pos = g_rowptr[d] + atomicAdd(&g_cnt[d], 1);
        g_col[pos] = s;
    }
}

// ---------------- SGEMM: g_h[M,256] = A[M,K] @ B[K,256] ----------------
#define BM 128
#define BN 128
#define BK 8
__global__ __launch_bounds__(256) void sgemm(const float* __restrict__ Aext,
                                             int a_sel,   // -1: use Aext, else buf_sel
                                             const float* __restrict__ B,
                                             int K) {
    const float* A = (a_sel < 0) ? Aext : buf_sel(a_sel);
    float* C = g_h;
    const int M = N_NODES;
    const int N = 256;
    __shared__ float As[BK][BM + 4];
    __shared__ float Bs[BK][BN];
    int tid = threadIdx.x;
    int bm = blockIdx.y, bn = blockIdx.x;

    int aRow = (tid >> 1);            // 0..127
    int aK   = (tid & 1) * 4;         // 0 or 4
    int gRowA = bm * BM + aRow;
    int bRow = (tid >> 5);            // 0..7
    int bCol = (tid & 31) * 4;        // 0..124

    int rowSeg = (tid >> 4) * 8;      // 0..120
    int colSeg = (tid & 15) * 8;      // 0..120

    float acc[8][8];
#pragma unroll
    for (int i = 0; i < 8; i++)
#pragma unroll
        for (int j = 0; j < 8; j++) acc[i][j] = 0.0f;

    for (int k0 = 0; k0 < K; k0 += BK) {
        float4 av = make_float4(0.f, 0.f, 0.f, 0.f);
        if (gRowA < M)
            av = *(const float4*)(A + (size_t)gRowA * K + k0 + aK);
        As[aK + 0][aRow] = av.x;
        As[aK + 1][aRow] = av.y;
        As[aK + 2][aRow] = av.z;
        As[aK + 3][aRow] = av.w;

        float4 bv = *(const float4*)(B + (size_t)(k0 + bRow) * N + bn * BN + bCol);
        *(float4*)&Bs[bRow][bCol] = bv;
        __syncthreads();

#pragma unroll
        for (int k = 0; k < BK; k++) {
            float a[8], b[8];
#pragma unroll
            for (int i = 0; i < 8; i++) a[i] = As[k][rowSeg + i];
#pragma unroll
            for (int j = 0; j < 8; j++) b[j] = Bs[k][colSeg + j];
#pragma unroll
            for (int i = 0; i < 8; i++)
#pragma unroll
                for (int j = 0; j < 8; j++) acc[i][j] = fmaf(a[i], b[j], acc[i][j]);
        }
        __syncthreads();
    }

#pragma unroll
    for (int i = 0; i < 8; i++) {
        int r = bm * BM + rowSeg + i;
        if (r < M) {
            float* cp = C + (size_t)r * N + bn * BN + colSeg;
            *(float4*)(cp + 0) = make_float4(acc[i][0], acc[i][1], acc[i][2], acc[i][3]);
            *(float4*)(cp + 4) = make_float4(acc[i][4], acc[i][5], acc[i][6], acc[i][7]);
        }
    }
}

// ---------------- attention logits: al[n][h] = sum_c h[n,h,c]*a[h,c] ----------------
__global__ __launch_bounds__(256) void compute_al(const float* __restrict__ a_src,
                                                  const float* __restrict__ a_dst) {
    int v = blockIdx.x;
    int w = threadIdx.x >> 5;   // head
    int lane = threadIdx.x & 31;
    float hv = g_h[(size_t)v * HID + w * CH + lane];
    float s1 = hv * a_src[w * CH + lane];
    float s2 = hv * a_dst[w * CH + lane];
#pragma unroll
    for (int off = 16; off; off >>= 1) {
        s1 += __shfl_xor_sync(0xffffffffu, s1, off);
        s2 += __shfl_xor_sync(0xffffffffu, s2, off);
    }
    if (lane == 0) {
        g_als[v * HEADS + w] = s1;
        g_ald[v * HEADS + w] = s2;
    }
}

// ---------------- warp-per-node softmax attention aggregation ----------------
__global__ __launch_bounds__(256) void gat_aggregate(const float* __restrict__ bias,
                                                     int out_sel) {
    const float* h = g_h;
    float* out = buf_sel(out_sel);
    int warp = (blockIdx.x * blockDim.x + threadIdx.x) >> 5;
    int lane = threadIdx.x & 31;
    if (warp >= N_NODES) return;
    int v = warp;
    int r0 = g_rowptr[v];
    int deg = g_rowptr[v + 1] - r0;     // +1 implicit self loop

    float ald[HEADS];
#pragma unroll
    for (int k = 0; k < HEADS; k++) ald[k] = g_ald[v * HEADS + k];

    // pass 1: per-head max over incoming edges (incl. self loop)
    float m[HEADS];
#pragma unroll
    for (int k = 0; k < HEADS; k++) m[k] = -1e30f;
    for (int i = lane; i < deg + 1; i += 32) {
        int s = (i < deg) ? g_col[r0 + i] : v;
#pragma unroll
        for (int k = 0; k < HEADS; k++) {
            float e = g_als[s * HEADS + k] + ald[k];
            e = (e > 0.f) ? e : SLOPE * e;
            m[k] = fmaxf(m[k], e);
        }
    }
#pragma unroll
    for (int k = 0; k < HEADS; k++)
#pragma unroll
        for (int off = 16; off; off >>= 1)
            m[k] = fmaxf(m[k], __shfl_xor_sync(0xffffffffu, m[k], off));

    // pass 2: fused exp-sum + weighted accumulation (normalize at end)
    float acc[HEADS];
#pragma unroll
    for (int k = 0; k < HEADS; k++) acc[k] = 0.0f;
    float denom = 0.0f;
    for (int i = 0; i < deg + 1; i++) {
        int s = (i < deg) ? g_col[r0 + i] : v;   // uniform across warp
        float ex = 0.0f;
        if (lane < HEADS) {
            float e = g_als[s * HEADS + lane] + ald[lane];
            e = (e > 0.f) ? e : SLOPE * e;
            ex = __expf(e - m[lane]);
            denom += ex;
        }
        const float* hs = h + (size_t)s * HID;
#pragma unroll
        for (int k = 0; k < HEADS; k++) {
            float exk = __shfl_sync(0xffffffffu, ex, k);
            acc[k] = fmaf(exk, hs[k * CH + lane], acc[k]);
        }
    }
#pragma unroll
    for (int k = 0; k < HEADS; k++) {
        float dk = __shfl_sync(0xffffffffu, denom, k);
        out[(size_t)v * HID + k * CH + lane] = acc[k] / (dk + 1e-16f) + bias[k * CH + lane];
    }
}

// ---------------- mean pool (sorted batch) + final linear, fused ----------------
__device__ __forceinline__ int lower_bound_idx(const int* __restrict__ w, int key, int is64) {
    int lo = 0, hi = N_NODES;
    while (lo < hi) {
        int mid = (lo + hi) >> 1;
        if (ld_idx(w, mid, is64) < key) lo = mid + 1; else hi = mid;
    }
    return lo;
}

__global__ __launch_bounds__(256) void pool_linear(const int* __restrict__ batch_w,
                                                   const float* __restrict__ Wl,
                                                   const float* __restrict__ bl,
                                                   float* __restrict__ out,
                                                   int feat_sel) {
    const float* feat = buf_sel(feat_sel);
    int is64 = g_is64_batch;
    int g = blockIdx.x;           // 0..127
    int tid = threadIdx.x;        // channel
    int start = lower_bound_idx(batch_w, g, is64);
    int end   = lower_bound_idx(batch_w, g + 1, is64);
    float acc = 0.0f;
    for (int n = start; n < end; n++) acc += feat[(size_t)n * HID + tid];
    int cnt = end - start;
    float pooled = acc / fmaxf((float)cnt, 1.0f);
    __shared__ float sp[HID];
    sp[tid] = pooled;
    __syncthreads();
    if (tid < OUT_DIM) {
        float o = bl[tid];
        for (int c = 0; c < HID; c++) o = fmaf(sp[c], Wl[c * OUT_DIM + tid], o);
        out[g * OUT_DIM + tid] = o;
    }
}

// ---------------- host launch ----------------
extern "C" void kernel_launch(void* const* d_in, const int* in_sizes, int n_in,
                              void* d_out, int out_size) {
    const float* x       = (const float*)d_in[0];
    const int*   ei_w    = (const int*)d_in[1];    // edge_index as 32-bit words
    const int*   batch_w = (const int*)d_in[2];    // batch as 32-bit words
    const float* W0      = (const float*)d_in[3];
    const float* as0     = (const float*)d_in[4];
    const float* ad0     = (const float*)d_in[5];
    const float* b0      = (const float*)d_in[6];
    const float* Wh      = (const float*)d_in[7];   // [2,256,256]
    const float* ash     = (const float*)d_in[8];   // [2,8,32]
    const float* adh     = (const float*)d_in[9];
    const float* bh      = (const float*)d_in[10];  // [2,256]
    const float* Wl      = (const float*)d_in[11];
    const float* bl      = (const float*)d_in[12];
    float*       out     = (float*)d_out;

    const int ZB = (N_NODES + 255) / 256;
    const int EB = (N_EDGES + 255) / 256;
    const int SB = (N_NODES + 1023) / 1024;   // 49

    // ---- dtype detect + CSR build (dst-sorted adjacency) ----
    detect_dtype<<<1, 1>>>(ei_w, batch_w);
    zero_cnt<<<ZB, 256>>>();
    hist_kernel<<<EB, 256>>>(ei_w);
    scan_block<<<SB, 1024>>>();
    scan_top<<<1, 64>>>(SB);
    scan_add<<<SB, 1024>>>();
    zero_cnt<<<ZB, 256>>>();
    scatter_kernel<<<EB, 256>>>(ei_w);

    dim3 gemm_grid(2, (N_NODES + BM - 1) / BM);
    const int AGG_B = (N_NODES * 32 + 255) / 256;   // warp per node

    // ---- layer 0: x -> g_h -> g_fa ----
    sgemm<<<gemm_grid, 256>>>(x, -1, W0, NF);
    compute_al<<<N_NODES, 256>>>(as0, ad0);
    gat_aggregate<<<AGG_B, 256>>>(b0, 1);

    // ---- layer 1: g_fa -> g_h -> g_fb ----
    sgemm<<<gemm_grid, 256>>>(nullptr, 1, Wh, HID);
    compute_al<<<N_NODES, 256>>>(ash, adh);
    gat_aggregate<<<AGG_B, 256>>>(bh, 2);

    // ---- layer 2: g_fb -> g_h -> g_fa ----
    sgemm<<<gemm_grid, 256>>>(nullptr, 2, Wh + HID * HID, HID);
    compute_al<<<N_NODES, 256>>>(ash + HEADS * CH, adh + HEADS * CH);
    gat_aggregate<<<AGG_B, 256>>>(bh + HID, 1);

    // ---- pool + linear ----
    pool_linear<<<NG, 256>>>(batch_w, Wl, bl, out, 1);
}